// round 7
// baseline (speedup 1.0000x reference)
#include <cuda_runtime.h>
#include <cuda_fp16.h>
#include <stdint.h>

#define M_DIM 2048
#define N_DIM 11008
#define K_DIM 4096

#define BM 128
#define BN 128
#define BK 32
#define KT (K_DIM / BK)          // 128
#define STAGES 3
#define A_STRIDE 160             // bytes per A row (64 data + 96 pad; bank-clean)
#define A_STG (BM * A_STRIDE)    // 20480
#define SMEM_TOTAL (STAGES * A_STG)  // 61440

__device__ __half g_xh[(size_t)M_DIM * K_DIM];

// ---------------------------------------------------------------------------
__global__ void convert_x_kernel(const float* __restrict__ x) {
    size_t i = ((size_t)blockIdx.x * blockDim.x + threadIdx.x) * 8;
    float4 f0 = *(const float4*)(x + i);
    float4 f1 = *(const float4*)(x + i + 4);
    __half2 h01 = __floats2half2_rn(f0.x, f0.y);
    __half2 h23 = __floats2half2_rn(f0.z, f0.w);
    __half2 h45 = __floats2half2_rn(f1.x, f1.y);
    __half2 h67 = __floats2half2_rn(f1.z, f1.w);
    uint4 v;
    v.x = *(uint32_t*)&h01; v.y = *(uint32_t*)&h23;
    v.z = *(uint32_t*)&h45; v.w = *(uint32_t*)&h67;
    *(uint4*)(g_xh + i) = v;
}

// ---------------------------------------------------------------------------
__device__ __forceinline__ uint32_t smem_u32(const void* p) {
    return (uint32_t)__cvta_generic_to_shared(p);
}
__device__ __forceinline__ void lds64(uint32_t& lo, uint32_t& hi, uint32_t a) {
    asm volatile("ld.shared.v2.u32 {%0,%1}, [%2];" : "=r"(lo), "=r"(hi) : "r"(a));
}
__device__ __forceinline__ void mma_16816(float c[4], const uint32_t a[4],
                                          const uint32_t b[2]) {
    asm volatile(
        "mma.sync.aligned.m16n8k16.row.col.f32.f16.f16.f32 "
        "{%0,%1,%2,%3}, {%4,%5,%6,%7}, {%8,%9}, {%0,%1,%2,%3};"
        : "+f"(c[0]), "+f"(c[1]), "+f"(c[2]), "+f"(c[3])
        : "r"(a[0]), "r"(a[1]), "r"(a[2]), "r"(a[3]), "r"(b[0]), "r"(b[1]));
}
__device__ __forceinline__ void cp16(uint32_t dst, const void* src) {
    asm volatile("cp.async.cg.shared.global [%0], [%1], 16;"
                 :: "r"(dst), "l"(src) : "memory");
}

// ---------------------------------------------------------------------------
// out[m,n] = scale[n]*sum_k x[m,k]*(W[k,n]-zero[n]) + bias[n]
// block 128x128, 8 warps (4m x 2n), warp tile 32x64, BK=32.
// B fragments built directly from packed gmem words (k-permuted MMA);
// A k-major in smem via cp.async (3 stages), fragments via LDS.64.
// ---------------------------------------------------------------------------
__global__ void __launch_bounds__(256, 2)
qgemm_kernel(const uint32_t* __restrict__ qw, const float* __restrict__ scales,
             const int* __restrict__ zeros, const float* __restrict__ bias,
             float* __restrict__ out) {
    extern __shared__ char smem[];
    const uint32_t sbase = smem_u32(smem);

    const int tid = threadIdx.x;
    const int lane = tid & 31;
    const int wid = tid >> 5;
    const int warp_m = wid & 3;   // 0..3 -> 32-row slabs
    const int warp_n = wid >> 2;  // 0..1 -> 64-col slabs
    const int bm0 = blockIdx.x * BM;
    const int bn0 = blockIdx.y * BN;

    // ---- A fill mapping (cp.async): 2 threads per row, 32B each ----
    const int rowA = tid >> 1;
    const int halfA = tid & 1;
    const __half* Ag = g_xh + (size_t)(bm0 + rowA) * K_DIM + halfA * 16;

    // ---- B fragment gmem base: lane owns (k4 = lane%4, n = lane/4) ----
    const int nb = bn0 + warp_n * 64 + (lane >> 2);
    const uint32_t* Bg = qw + (size_t)(lane & 3) * N_DIM + nb;

    __half2 zc[8];
#pragma unroll
    for (int nj = 0; nj < 8; nj++)
        zc[nj] = __half2half2(
            __float2half_rn(1024.0f + (float)zeros[nb + nj * 8]));

    float acc[2][8][4];
#pragma unroll
    for (int mi = 0; mi < 2; mi++)
#pragma unroll
        for (int ni = 0; ni < 8; ni++)
#pragma unroll
            for (int t = 0; t < 4; t++) acc[mi][ni][t] = 0.0f;

#define FILL_A(S, KTILE)                                                       \
    do {                                                                       \
        uint32_t db = sbase + (uint32_t)((S) * A_STG + rowA * A_STRIDE +       \
                                         halfA * 32);                          \
        const __half* sp = Ag + (KTILE) * BK;                                  \
        cp16(db, sp);                                                          \
        cp16(db + 16, sp + 8);                                                 \
        asm volatile("cp.async.commit_group;" ::: "memory");                   \
    } while (0)

    // ---- prologue ----
    FILL_A(0, 0);
    FILL_A(1, 1);
    uint32_t br[2][8];   // [k16][nj] packed words, current tile
#pragma unroll
    for (int g = 0; g < 2; g++)
#pragma unroll
        for (int nj = 0; nj < 8; nj++)
            br[g][nj] = Bg[(size_t)(g * 4) * N_DIM + nj * 8];
    asm volatile("cp.async.wait_group 1;" ::: "memory");
    __syncthreads();

    const int arow = lane >> 2;       // 0..7
    const int acol = (lane & 3) * 8;  // byte offset within 32B k16 block

#pragma unroll 1
    for (int kt = 0; kt < KT; kt++) {
        if (kt + 2 < KT) FILL_A((kt + 2) % STAGES, kt + 2);
        const uint32_t abase = sbase + (uint32_t)((kt % STAGES) * A_STG) +
                               (uint32_t)(warp_m * 32 + arow) * A_STRIDE + acol;
        const int ktn = (kt + 1) & (KT - 1);   // next tile (wraps, harmless)

#pragma unroll
        for (int g = 0; g < 2; g++) {
            // A fragments: slot-k = 16*g + 4*(lane%4) + {0..3}
            uint32_t af[2][4];
#pragma unroll
            for (int mi = 0; mi < 2; mi++) {
                uint32_t a0 = abase + (uint32_t)(mi * 16) * A_STRIDE + g * 32;
                uint32_t lo0, hi0, lo1, hi1;
                lds64(lo0, hi0, a0);
                lds64(lo1, hi1, a0 + 8 * A_STRIDE);
                af[mi][0] = lo0; af[mi][1] = lo1;
                af[mi][2] = hi0; af[mi][3] = hi1;
            }
            // B fragments: in-register dequant, then prefetch next tile word
#pragma unroll
            for (int nj = 0; nj < 8; nj++) {
                uint32_t w = br[g][nj];
                uint32_t lo = __byte_perm(w, 0x64646464u, 0x4140);
                uint32_t hi = __byte_perm(w, 0x64646464u, 0x4342);
                __half2 h0 = __hsub2(*(__half2*)&lo, zc[nj]);
                __half2 h1 = __hsub2(*(__half2*)&hi, zc[nj]);
                uint32_t bf[2];
                bf[0] = *(uint32_t*)&h0;
                bf[1] = *(uint32_t*)&h1;
                br[g][nj] = Bg[(size_t)(ktn * 8 + g * 4) * N_DIM + nj * 8];
#pragma unroll
                for (int mi = 0; mi < 2; mi++)
                    mma_16816(acc[mi][nj], af[mi], bf);
            }
        }

        if (kt + 2 < KT) {
            asm volatile("cp.async.wait_group 1;" ::: "memory");
        } else {
            asm volatile("cp.async.wait_group 0;" ::: "memory");
        }
        __syncthreads();
    }

    // ---- epilogue ----
    const int m0 = bm0 + warp_m * 32;
    const int n0w = bn0 + warp_n * 64;
    const int elr = lane >> 2;
    const int elc = (lane & 3) * 2;
#pragma unroll
    for (int ni = 0; ni < 8; ni++) {
        const int col = n0w + ni * 8 + elc;
        const float s0 = scales[col], s1 = scales[col + 1];
        const float b0 = bias[col], b1 = bias[col + 1];
#pragma unroll
        for (int mi = 0; mi < 2; mi++) {
            const int r0 = m0 + mi * 16 + elr;
            float2 v0 = make_float2(acc[mi][ni][0] * s0 + b0,
                                    acc[mi][ni][1] * s1 + b1);
            *(float2*)(out + (size_t)r0 * N_DIM + col) = v0;
            float2 v1 = make_float2(acc[mi][ni][2] * s0 + b0,
                                    acc[mi][ni][3] * s1 + b1);
            *(float2*)(out + (size_t)(r0 + 8) * N_DIM + col) = v1;
        }
    }
}

// ---------------------------------------------------------------------------
extern "C" void kernel_launch(void* const* d_in, const int* in_sizes, int n_in,
                              void* d_out, int out_size) {
    const float* x = (const float*)d_in[0];
    const uint32_t* qw = (const uint32_t*)d_in[1];
    const float* scales = (const float*)d_in[2];
    const int* zeros = (const int*)d_in[3];
    const float* bias = (const float*)d_in[4];
    float* out = (float*)d_out;

    convert_x_kernel<<<(M_DIM * K_DIM) / (256 * 8), 256>>>(x);

    cudaFuncSetAttribute(qgemm_kernel,
                         cudaFuncAttributeMaxDynamicSharedMemorySize, SMEM_TOTAL);
    dim3 grid(M_DIM / BM, N_DIM / BN);  // 16 x 86 (m fastest: B L2 reuse)
    qgemm_kernel<<<grid, 256, SMEM_TOTAL>>>(qw, scales, zeros, bias, out);
}

// round 8
// speedup vs baseline: 1.0891x; 1.0891x over previous
#include <cuda_runtime.h>
#include <cuda_fp16.h>
#include <stdint.h>

#define M_DIM 2048
#define N_DIM 11008
#define K_DIM 4096

#define BM 128
#define BN 128
#define BK 32
#define KT (K_DIM / BK)          // 128
#define STAGES 3
#define A_STRIDE 160             // bytes per A row (64 data + 96 pad; bank-clean)
#define A_STG (BM * A_STRIDE)    // 20480
#define SMEM_TOTAL (STAGES * A_STG)  // 61440

__device__ __half g_xh[(size_t)M_DIM * K_DIM];

// ---------------------------------------------------------------------------
__global__ void convert_x_kernel(const float* __restrict__ x) {
    size_t i = ((size_t)blockIdx.x * blockDim.x + threadIdx.x) * 8;
    float4 f0 = *(const float4*)(x + i);
    float4 f1 = *(const float4*)(x + i + 4);
    __half2 h01 = __floats2half2_rn(f0.x, f0.y);
    __half2 h23 = __floats2half2_rn(f0.z, f0.w);
    __half2 h45 = __floats2half2_rn(f1.x, f1.y);
    __half2 h67 = __floats2half2_rn(f1.z, f1.w);
    uint4 v;
    v.x = *(uint32_t*)&h01; v.y = *(uint32_t*)&h23;
    v.z = *(uint32_t*)&h45; v.w = *(uint32_t*)&h67;
    *(uint4*)(g_xh + i) = v;
}

// ---------------------------------------------------------------------------
__device__ __forceinline__ uint32_t smem_u32(const void* p) {
    return (uint32_t)__cvta_generic_to_shared(p);
}
__device__ __forceinline__ void lds64(uint32_t& lo, uint32_t& hi, uint32_t a) {
    asm volatile("ld.shared.v2.u32 {%0,%1}, [%2];" : "=r"(lo), "=r"(hi) : "r"(a));
}
__device__ __forceinline__ void mma_16816(float c[4], const uint32_t a[4],
                                          const uint32_t b[2]) {
    asm volatile(
        "mma.sync.aligned.m16n8k16.row.col.f32.f16.f16.f32 "
        "{%0,%1,%2,%3}, {%4,%5,%6,%7}, {%8,%9}, {%0,%1,%2,%3};"
        : "+f"(c[0]), "+f"(c[1]), "+f"(c[2]), "+f"(c[3])
        : "r"(a[0]), "r"(a[1]), "r"(a[2]), "r"(a[3]), "r"(b[0]), "r"(b[1]));
}
__device__ __forceinline__ void cp16(uint32_t dst, const void* src) {
    asm volatile("cp.async.cg.shared.global [%0], [%1], 16;"
                 :: "r"(dst), "l"(src) : "memory");
}

// ---------------------------------------------------------------------------
// out[m,n] = scale[n]*sum_k x[m,k]*(W[k,n]-zero[n]) + bias[n]
// block 128x128, 8 warps (2m x 4n), warp tile 64x32, BK=32, 2 CTAs/SM.
// B fragments built directly from packed gmem words (k-permuted MMA);
// A k-major in smem via cp.async (3 stages), fragments via LDS.64.
// ---------------------------------------------------------------------------
__global__ void __launch_bounds__(256, 2)
qgemm_kernel(const uint32_t* __restrict__ qw, const float* __restrict__ scales,
             const int* __restrict__ zeros, const float* __restrict__ bias,
             float* __restrict__ out) {
    extern __shared__ char smem[];
    const uint32_t sbase = smem_u32(smem);

    const int tid = threadIdx.x;
    const int lane = tid & 31;
    const int wid = tid >> 5;
    const int warp_m = wid & 1;   // 0..1 -> 64-row slabs
    const int warp_n = wid >> 1;  // 0..3 -> 32-col slabs
    const int bm0 = blockIdx.x * BM;
    const int bn0 = blockIdx.y * BN;

    // ---- A fill mapping (cp.async): 2 threads per row, 32B each ----
    const int rowA = tid >> 1;
    const int halfA = tid & 1;
    const __half* Ag = g_xh + (size_t)(bm0 + rowA) * K_DIM + halfA * 16;

    // ---- B fragment gmem base: lane owns (k4 = lane%4, n = lane/4) ----
    const int nb = bn0 + warp_n * 32 + (lane >> 2);
    const uint32_t* Bg = qw + (size_t)(lane & 3) * N_DIM + nb;

    __half2 zc[4];
#pragma unroll
    for (int nj = 0; nj < 4; nj++)
        zc[nj] = __half2half2(
            __float2half_rn(1024.0f + (float)zeros[nb + nj * 8]));

    float acc[4][4][4];
#pragma unroll
    for (int mi = 0; mi < 4; mi++)
#pragma unroll
        for (int ni = 0; ni < 4; ni++)
#pragma unroll
            for (int t = 0; t < 4; t++) acc[mi][ni][t] = 0.0f;

#define FILL_A(S, KTILE)                                                       \
    do {                                                                       \
        uint32_t db = sbase + (uint32_t)((S) * A_STG + rowA * A_STRIDE +       \
                                         halfA * 32);                          \
        const __half* sp = Ag + (KTILE) * BK;                                  \
        cp16(db, sp);                                                          \
        cp16(db + 16, sp + 8);                                                 \
        asm volatile("cp.async.commit_group;" ::: "memory");                   \
    } while (0)

    // ---- prologue ----
    FILL_A(0, 0);
    FILL_A(1, 1);
    uint32_t br[2][4];   // [k16][nj] packed words, current tile
#pragma unroll
    for (int g = 0; g < 2; g++)
#pragma unroll
        for (int nj = 0; nj < 4; nj++)
            br[g][nj] = Bg[(size_t)(g * 4) * N_DIM + nj * 8];
    asm volatile("cp.async.wait_group 1;" ::: "memory");
    __syncthreads();

    const int arow = lane >> 2;       // 0..7
    const int acol = (lane & 3) * 8;  // byte offset within 32B k16 block

#pragma unroll 1
    for (int kt = 0; kt < KT; kt++) {
        if (kt + 2 < KT) FILL_A((kt + 2) % STAGES, kt + 2);
        const uint32_t abase = sbase + (uint32_t)((kt % STAGES) * A_STG) +
                               (uint32_t)(warp_m * 64 + arow) * A_STRIDE + acol;
        const int ktn = (kt + 1) & (KT - 1);   // next tile (wraps, harmless)

#pragma unroll
        for (int g = 0; g < 2; g++) {
            // A fragments: slot-k = 16*g + 4*(lane%4) + {0..3}
            uint32_t af[4][4];
#pragma unroll
            for (int mi = 0; mi < 4; mi++) {
                uint32_t a0 = abase + (uint32_t)(mi * 16) * A_STRIDE + g * 32;
                uint32_t lo0, hi0, lo1, hi1;
                lds64(lo0, hi0, a0);
                lds64(lo1, hi1, a0 + 8 * A_STRIDE);
                af[mi][0] = lo0; af[mi][1] = lo1;
                af[mi][2] = hi0; af[mi][3] = hi1;
            }
            // B fragments: in-register dequant, then prefetch next tile word
#pragma unroll
            for (int nj = 0; nj < 4; nj++) {
                uint32_t w = br[g][nj];
                uint32_t lo = __byte_perm(w, 0x64646464u, 0x4140);
                uint32_t hi = __byte_perm(w, 0x64646464u, 0x4342);
                __half2 h0 = __hsub2(*(__half2*)&lo, zc[nj]);
                __half2 h1 = __hsub2(*(__half2*)&hi, zc[nj]);
                uint32_t bf[2];
                bf[0] = *(uint32_t*)&h0;
                bf[1] = *(uint32_t*)&h1;
                br[g][nj] = Bg[(size_t)(ktn * 8 + g * 4) * N_DIM + nj * 8];
#pragma unroll
                for (int mi = 0; mi < 4; mi++)
                    mma_16816(acc[mi][nj], af[mi], bf);
            }
        }

        if (kt + 2 < KT) {
            asm volatile("cp.async.wait_group 1;" ::: "memory");
        } else {
            asm volatile("cp.async.wait_group 0;" ::: "memory");
        }
        __syncthreads();
    }

    // ---- epilogue ----
    const int m0 = bm0 + warp_m * 64;
    const int n0w = bn0 + warp_n * 32;
    const int elr = lane >> 2;
    const int elc = (lane & 3) * 2;
#pragma unroll
    for (int ni = 0; ni < 4; ni++) {
        const int col = n0w + ni * 8 + elc;
        const float s0 = scales[col], s1 = scales[col + 1];
        const float b0 = bias[col], b1 = bias[col + 1];
#pragma unroll
        for (int mi = 0; mi < 4; mi++) {
            const int r0 = m0 + mi * 16 + elr;
            float2 v0 = make_float2(acc[mi][ni][0] * s0 + b0,
                                    acc[mi][ni][1] * s1 + b1);
            *(float2*)(out + (size_t)r0 * N_DIM + col) = v0;
            float2 v1 = make_float2(acc[mi][ni][2] * s0 + b0,
                                    acc[mi][ni][3] * s1 + b1);
            *(float2*)(out + (size_t)(r0 + 8) * N_DIM + col) = v1;
        }
    }
}

// ---------------------------------------------------------------------------
extern "C" void kernel_launch(void* const* d_in, const int* in_sizes, int n_in,
                              void* d_out, int out_size) {
    const float* x = (const float*)d_in[0];
    const uint32_t* qw = (const uint32_t*)d_in[1];
    const float* scales = (const float*)d_in[2];
    const int* zeros = (const int*)d_in[3];
    const float* bias = (const float*)d_in[4];
    float* out = (float*)d_out;

    convert_x_kernel<<<(M_DIM * K_DIM) / (256 * 8), 256>>>(x);

    cudaFuncSetAttribute(qgemm_kernel,
                         cudaFuncAttributeMaxDynamicSharedMemorySize, SMEM_TOTAL);
    dim3 grid(M_DIM / BM, N_DIM / BN);  // 16 x 86 (m fastest: B L2 reuse)
    qgemm_kernel<<<grid, 256, SMEM_TOTAL>>>(qw, scales, zeros, bias, out);
}

// round 9
// speedup vs baseline: 1.1451x; 1.0514x over previous
#include <cuda_runtime.h>
#include <cuda_fp16.h>
#include <stdint.h>

#define M_DIM 2048
#define N_DIM 11008
#define K_DIM 4096
#define K16   (K_DIM / 16)       // 256

#define BM 128
#define BN 128
#define BK 64
#define KT (K_DIM / BK)          // 64
#define STAGES 4
#define STG_BYTES 16384          // 8 m16-tiles * 4 k16 * 512B
#define SMEM_TOTAL (STAGES * STG_BYTES)  // 65536

// A in fragment-major layout: uint4 chunk per (m16, k16, lane)
__device__ uint4 g_xa[(size_t)(M_DIM / 16) * K16 * 32];

// ---------------------------------------------------------------------------
// convert: x f32 -> fragment-major fp16 chunks.
// chunk(m16,k16,lane): {h(x[r][k0]),h(x[r][k0+1])} {row r+8 same} {r, k0+2,k0+3} {r+8}
//   r = m16*16 + lane/4,  k0 = k16*16 + 4*(lane%4)
// ---------------------------------------------------------------------------
__global__ void convert_x_kernel(const float* __restrict__ x) {
    int gid = blockIdx.x * blockDim.x + threadIdx.x;   // 0 .. 2^20-1
    int lane = gid & 31;
    int k16 = (gid >> 5) & (K16 - 1);
    int m16 = gid >> 13;
    int r = m16 * 16 + (lane >> 2);
    int k0 = k16 * 16 + (lane & 3) * 4;
    float4 p = *(const float4*)(x + (size_t)r * K_DIM + k0);
    float4 q = *(const float4*)(x + (size_t)(r + 8) * K_DIM + k0);
    __half2 u0 = __floats2half2_rn(p.x, p.y);
    __half2 u1 = __floats2half2_rn(q.x, q.y);
    __half2 u2 = __floats2half2_rn(p.z, p.w);
    __half2 u3 = __floats2half2_rn(q.z, q.w);
    uint4 v;
    v.x = *(uint32_t*)&u0; v.y = *(uint32_t*)&u1;
    v.z = *(uint32_t*)&u2; v.w = *(uint32_t*)&u3;
    g_xa[gid] = v;
}

// ---------------------------------------------------------------------------
__device__ __forceinline__ uint32_t smem_u32(const void* p) {
    return (uint32_t)__cvta_generic_to_shared(p);
}
__device__ __forceinline__ void lds128(uint32_t* r, uint32_t a) {
    asm volatile("ld.shared.v4.u32 {%0,%1,%2,%3}, [%4];"
                 : "=r"(r[0]), "=r"(r[1]), "=r"(r[2]), "=r"(r[3]) : "r"(a));
}
__device__ __forceinline__ void mma_16816(float c[4], const uint32_t a[4],
                                          const uint32_t b[2]) {
    asm volatile(
        "mma.sync.aligned.m16n8k16.row.col.f32.f16.f16.f32 "
        "{%0,%1,%2,%3}, {%4,%5,%6,%7}, {%8,%9}, {%0,%1,%2,%3};"
        : "+f"(c[0]), "+f"(c[1]), "+f"(c[2]), "+f"(c[3])
        : "r"(a[0]), "r"(a[1]), "r"(a[2]), "r"(a[3]), "r"(b[0]), "r"(b[1]));
}
__device__ __forceinline__ void cp16(uint32_t dst, const void* src) {
    asm volatile("cp.async.cg.shared.global [%0], [%1], 16;"
                 :: "r"(dst), "l"(src) : "memory");
}

// ---------------------------------------------------------------------------
// out[m,n] = scale[n]*sum_k x[m,k]*(W[k,n]-zero[n]) + bias[n]
// block 128x128, 8 warps (2m x 4n), warp tile 64x32, BK=64, 4-stage, 2 CTAs/SM.
// A: fragment-major smem (1 LDS.128 per fragment). B: direct-from-gmem dequant.
// ---------------------------------------------------------------------------
__global__ void __launch_bounds__(256, 2)
qgemm_kernel(const uint32_t* __restrict__ qw, const float* __restrict__ scales,
             const int* __restrict__ zeros, const float* __restrict__ bias,
             float* __restrict__ out) {
    extern __shared__ char smem[];
    const uint32_t sbase = smem_u32(smem);

    const int tid = threadIdx.x;
    const int lane = tid & 31;
    const int wid = tid >> 5;
    const int warp_m = wid & 1;   // 0..1 -> 64-row slabs
    const int warp_n = wid >> 1;  // 0..3 -> 32-col slabs
    const int bm0 = blockIdx.x * BM;
    const int bn0 = blockIdx.y * BN;

    // ---- A fill: 64B per thread, linear block copy ----
    // stage layout: (m16_local*4 + k16_local)*512 + lane*16
    const int m16l_f = tid >> 5;            // tid/32 = m16_local (0..7)
    const int rem4_f = (tid & 31) * 4;      // uint4 index within 2KB region
    const uint4* Agbase = g_xa + ((size_t)(bm0 / 16 + m16l_f) * K16) * 32 + rem4_f;

    // ---- B fragment gmem base: lane owns (k4 = lane%4, n = lane/4) ----
    const int nb = bn0 + warp_n * 32 + (lane >> 2);
    const uint32_t* Bg = qw + (size_t)(lane & 3) * N_DIM + nb;

    __half2 zc[4];
#pragma unroll
    for (int nj = 0; nj < 4; nj++)
        zc[nj] = __half2half2(
            __float2half_rn(1024.0f + (float)zeros[nb + nj * 8]));

    float acc[4][4][4];
#pragma unroll
    for (int mi = 0; mi < 4; mi++)
#pragma unroll
        for (int ni = 0; ni < 4; ni++)
#pragma unroll
            for (int t = 0; t < 4; t++) acc[mi][ni][t] = 0.0f;

#define FILL_A(S, KTILE)                                                       \
    do {                                                                       \
        uint32_t db = sbase + (uint32_t)((S) * STG_BYTES + tid * 64);          \
        const uint4* sp = Agbase + (size_t)(KTILE) * 4 * 32;                   \
        cp16(db,      sp);                                                     \
        cp16(db + 16, sp + 1);                                                 \
        cp16(db + 32, sp + 2);                                                 \
        cp16(db + 48, sp + 3);                                                 \
        asm volatile("cp.async.commit_group;" ::: "memory");                   \
    } while (0)

    // ---- prologue ----
    FILL_A(0, 0);
    FILL_A(1, 1);
    FILL_A(2, 2);
    uint32_t br[2][4];   // ping-pong per k16
#pragma unroll
    for (int g = 0; g < 2; g++)
#pragma unroll
        for (int nj = 0; nj < 4; nj++)
            br[g][nj] = Bg[(size_t)(g * 4) * N_DIM + nj * 8];

    const uint32_t awbase = sbase + (uint32_t)(warp_m * 4 * 2048 + lane * 16);

#pragma unroll 1
    for (int kt = 0; kt < KT; kt++) {
        if (kt + 3 < KT) {
            asm volatile("cp.async.wait_group 2;" ::: "memory");
            __syncthreads();
            FILL_A((kt + 3) & 3, kt + 3);
        } else {
            asm volatile("cp.async.wait_group 0;" ::: "memory");
            __syncthreads();
        }
        const uint32_t abase = awbase + (uint32_t)((kt & 3) * STG_BYTES);
        const int ktn = (kt + 1) & (KT - 1);

#pragma unroll
        for (int g = 0; g < 4; g++) {
            // A fragments: one LDS.128 each
            uint32_t af[4][4];
#pragma unroll
            for (int mi = 0; mi < 4; mi++)
                lds128(af[mi], abase + (uint32_t)(mi * 2048 + g * 512));

            const int k16n = (g < 2) ? (kt * 4 + g + 2) : (ktn * 4 + g - 2);
            const int slot = g & 1;
#pragma unroll
            for (int nj = 0; nj < 4; nj++) {
                uint32_t w = br[slot][nj];
                uint32_t lo = __byte_perm(w, 0x64646464u, 0x4140);
                uint32_t hi = __byte_perm(w, 0x64646464u, 0x4342);
                __half2 h0 = __hsub2(*(__half2*)&lo, zc[nj]);
                __half2 h1 = __hsub2(*(__half2*)&hi, zc[nj]);
                uint32_t bf[2];
                bf[0] = *(uint32_t*)&h0;
                bf[1] = *(uint32_t*)&h1;
                br[slot][nj] = Bg[(size_t)(k16n * 4) * N_DIM + nj * 8];
#pragma unroll
                for (int mi = 0; mi < 4; mi++)
                    mma_16816(acc[mi][nj], af[mi], bf);
            }
        }
    }

    // ---- epilogue ----
    const int m0 = bm0 + warp_m * 64;
    const int n0w = bn0 + warp_n * 32;
    const int elr = lane >> 2;
    const int elc = (lane & 3) * 2;
#pragma unroll
    for (int ni = 0; ni < 4; ni++) {
        const int col = n0w + ni * 8 + elc;
        const float s0 = scales[col], s1 = scales[col + 1];
        const float b0 = bias[col], b1 = bias[col + 1];
#pragma unroll
        for (int mi = 0; mi < 4; mi++) {
            const int r0 = m0 + mi * 16 + elr;
            float2 v0 = make_float2(acc[mi][ni][0] * s0 + b0,
                                    acc[mi][ni][1] * s1 + b1);
            *(float2*)(out + (size_t)r0 * N_DIM + col) = v0;
            float2 v1 = make_float2(acc[mi][ni][2] * s0 + b0,
                                    acc[mi][ni][3] * s1 + b1);
            *(float2*)(out + (size_t)(r0 + 8) * N_DIM + col) = v1;
        }
    }
}

// ---------------------------------------------------------------------------
extern "C" void kernel_launch(void* const* d_in, const int* in_sizes, int n_in,
                              void* d_out, int out_size) {
    const float* x = (const float*)d_in[0];
    const uint32_t* qw = (const uint32_t*)d_in[1];
    const float* scales = (const float*)d_in[2];
    const int* zeros = (const int*)d_in[3];
    const float* bias = (const float*)d_in[4];
    float* out = (float*)d_out;

    convert_x_kernel<<<(M_DIM / 16) * K16 * 32 / 256, 256>>>(x);

    cudaFuncSetAttribute(qgemm_kernel,
                         cudaFuncAttributeMaxDynamicSharedMemorySize, SMEM_TOTAL);
    dim3 grid(M_DIM / BM, N_DIM / BN);  // 16 x 86 (m fastest: B L2 reuse)
    qgemm_kernel<<<grid, 256, SMEM_TOTAL>>>(qw, scales, zeros, bias, out);
}